// round 9
// baseline (speedup 1.0000x reference)
#include <cuda_runtime.h>

#define HW   4096
#define C    128
#define CR   32
#define G    8
#define CG   16
#define KK   49
#define KKG  392
#define NPX  16384   // B * H * W

typedef unsigned long long u64;

// ---- packed f32x2 helpers (sm_103a) ---------------------------------------
__device__ __forceinline__ u64 pack2(float x, float y) {
    u64 r; asm("mov.b64 %0, {%1, %2};" : "=l"(r) : "f"(x), "f"(y)); return r;
}
__device__ __forceinline__ void unpack2(u64 v, float& x, float& y) {
    asm("mov.b64 {%0, %1}, %2;" : "=f"(x), "=f"(y) : "l"(v));
}
__device__ __forceinline__ void ffma2(u64& d, u64 a, u64 b) {
    asm("fma.rn.f32x2 %0, %1, %2, %0;" : "+l"(d) : "l"(a), "l"(b));
}

// Scratch: reduce output, k-major so the fused kernel reads px-pairs as LDG.64
__device__ __align__(16) float g_red[CR * NPX];        // [k][px]

// ---------------------------------------------------------------------------
// Kernel 1: red[k][px] = sum_c x[b,c,hw] * w_reduce[k,c] + b_reduce[k]
// Block 256 thr = 8 warps; tile 64 px; warp computes 4 outs x 64 px.
// Everything staged once (x tile 32KB as px-pairs, w duplicated 34KB), 1 sync.
// Inner loop per k: 1 LDS.64 (a, lane-consec) + 4 LDS.64 bcast (w) + 4 FFMA2.
// ---------------------------------------------------------------------------
__global__ __launch_bounds__(256) void k_reduce(const float* __restrict__ x,
                                                const float* __restrict__ wr,
                                                const float* __restrict__ br) {
    __shared__ u64 xsd[C * 32];        // [c][p2]  (p2 = px pair 0..31), 32 KB
    __shared__ u64 wsd[C * 33];        // [c][o] duplicated (w,w), stride 33, 33.8 KB
    const int tid  = threadIdx.x;
    const int lane = tid & 31;
    const int warp = tid >> 5;
    const int px0  = blockIdx.x * 64;
    const int b    = px0 >> 12;
    const int hw0  = px0 & 4095;
    const float* xb = x + (size_t)b * C * HW + hw0;

    // stage x tile as pairs: coalesced float2 LDG, consecutive STS
#pragma unroll
    for (int l = 0; l < 16; l++) {
        int idx = tid + l * 256;               // 4096 = 128 c * 32 pairs
        int c = idx >> 5, p2 = idx & 31;
        float2 v = *(const float2*)&xb[(size_t)c * HW + 2 * p2];
        xsd[c * 32 + p2] = pack2(v.x, v.y);
    }
    // stage w duplicated: coalesced read (c fastest), stride-33 write (no conflict)
#pragma unroll
    for (int l = 0; l < 16; l++) {
        int idx = tid + l * 256;               // 4096 = 32 o * 128 c
        int c = idx & 127, o = idx >> 7;
        float v = wr[o * C + c];
        wsd[c * 33 + o] = pack2(v, v);
    }
    __syncthreads();

    const int wo = warp * 4;                   // warp's 4 output channels
    u64 acc[4];
#pragma unroll
    for (int j = 0; j < 4; j++) {
        float bj = br[wo + j];
        acc[j] = pack2(bj, bj);
    }

#pragma unroll 8
    for (int k = 0; k < C; k++) {
        const u64 a = xsd[k * 32 + lane];      // lane's px pair
#pragma unroll
        for (int j = 0; j < 4; j++)
            ffma2(acc[j], a, wsd[k * 33 + wo + j]);   // warp-uniform bcast
    }

#pragma unroll
    for (int j = 0; j < 4; j++) {
        float f0, f1; unpack2(acc[j], f0, f1);
        *(float2*)&g_red[(size_t)(wo + j) * NPX + px0 + 2 * lane] = make_float2(f0, f1);
    }
}

// ---------------------------------------------------------------------------
// Kernel 2 (FUSED span + involution). Block = 256 thr (16x16), 32x16 px tile,
// one (b, g) per z. Each thread owns 2 horizontal px.
// Phase 1 (span): kreg[49] (f32x2 pairs, bias-initialized) accumulated from
//   g_red px-pair LDG.64 * duplicated-w LDS.64 broadcast. ker never hits DRAM.
// Phase 2 (inv): identical to the proven R4 involution loop.
// ---------------------------------------------------------------------------
__global__ __launch_bounds__(256) void k_fused(const float* __restrict__ x,
                                               const float* __restrict__ wsp,
                                               const float* __restrict__ bs,
                                               float* __restrict__ out) {
    __shared__ u64 wsd[KK * 32];       // [o][k] duplicated (w,w), 12.5 KB
    __shared__ float xs[4][28][48];    // 4 channels, 28x44 patch (stride 48), 21.5 KB
    const int tx = threadIdx.x, ty = threadIdx.y;   // (16,16)
    const int tid = ty * 16 + tx;
    const int tx0 = blockIdx.x * 32, ty0 = blockIdx.y * 16;
    const int bg = blockIdx.z;
    const int b = bg >> 3, g = bg & 7;
    const int pix  = (ty0 + ty) * 64 + tx0 + 2 * tx;   // even -> 8B aligned
    const int gpix = b * HW + pix;                     // global px index

    // stage w_span for this group, duplicated: coalesced reads, consec writes
    const float* wg = wsp + (size_t)(g * KK) * 32;
#pragma unroll
    for (int l = 0; l < 7; l++) {
        int idx = tid + l * 256;               // 1568 = 49 * 32
        if (idx < KK * 32) {
            float v = wg[idx];
            wsd[idx] = pack2(v, v);
        }
    }
    __syncthreads();

    // ---- Phase 1: per-pixel dynamic kernel into registers -----------------
    u64 kreg[KK];
    const float* bsg = bs + g * KK;
#pragma unroll
    for (int o = 0; o < KK; o++) {
        float bv = bsg[o];
        kreg[o] = pack2(bv, bv);
    }

#pragma unroll 4
    for (int k = 0; k < 32; k++) {
        const u64 a = *(const u64*)&g_red[(size_t)k * NPX + gpix];  // px pair
#pragma unroll
        for (int o = 0; o < KK; o++)
            ffma2(kreg[o], a, wsd[o * 32 + k]);        // warp-uniform bcast
    }

    // ---- Phase 2: involution (R4-proven loop) -----------------------------
    const float* xb = x + ((size_t)b * C + g * CG) * HW;
    float* ob = out + ((size_t)b * C + g * CG) * HW + pix;

    for (int c0 = 0; c0 < CG; c0 += 4) {
        __syncthreads();
#pragma unroll
        for (int cc = 0; cc < 4; cc++) {
            const float* xc = xb + (size_t)(c0 + cc) * HW;
#pragma unroll
            for (int l = 0; l < 5; l++) {
                int idx = tid + l * 256;
                if (idx < 28 * 44) {
                    int r    = idx / 44;
                    int ccol = idx - r * 44;
                    int gy = ty0 - 6 + r;
                    int gx = tx0 - 6 + ccol;
                    float v = 0.f;
                    if (gy >= 0 && gy < 64 && gx >= 0 && gx < 64)
                        v = xc[gy * 64 + gx];
                    xs[cc][r][ccol] = v;
                }
            }
        }
        __syncthreads();

#pragma unroll
        for (int cc = 0; cc < 4; cc++) {
            u64 acc = 0;
#pragma unroll
            for (int i = 0; i < 7; i++)
#pragma unroll
                for (int j = 0; j < 7; j++) {
                    const u64 v = *(const u64*)&xs[cc][ty + 2 * i][2 * tx + 2 * j];
                    ffma2(acc, v, kreg[i * 7 + j]);
                }
            float f0, f1; unpack2(acc, f0, f1);
            *(float2*)&ob[(size_t)(c0 + cc) * HW] = make_float2(f0, f1);
        }
    }
}

// ---------------------------------------------------------------------------
extern "C" void kernel_launch(void* const* d_in, const int* in_sizes, int n_in,
                              void* d_out, int out_size) {
    const float* x   = (const float*)d_in[0];   // [4,128,64,64]
    const float* wr  = (const float*)d_in[1];   // [32,128]
    const float* br  = (const float*)d_in[2];   // [32]
    const float* wsp = (const float*)d_in[3];   // [392,32]
    const float* bsp = (const float*)d_in[4];   // [392]
    float* out = (float*)d_out;

    k_reduce<<<256, 256>>>(x, wr, br);
    k_fused<<<dim3(2, 4, 32), dim3(16, 16)>>>(x, wsp, bsp, out);
}

// round 10
// speedup vs baseline: 1.3348x; 1.3348x over previous
#include <cuda_runtime.h>

#define HW   4096
#define C    128
#define CR   32
#define G    8
#define CG   16
#define KK   49
#define KKG  392
#define NPX  16384   // B * H * W

typedef unsigned long long u64;

// ---- packed f32x2 helpers (sm_103a) ---------------------------------------
__device__ __forceinline__ u64 pack2(float x, float y) {
    u64 r; asm("mov.b64 %0, {%1, %2};" : "=l"(r) : "f"(x), "f"(y)); return r;
}
__device__ __forceinline__ void unpack2(u64 v, float& x, float& y) {
    asm("mov.b64 {%0, %1}, %2;" : "=f"(x), "=f"(y) : "l"(v));
}
__device__ __forceinline__ void ffma2(u64& d, u64 a, u64 b) {
    asm("fma.rn.f32x2 %0, %1, %2, %0;" : "+l"(d) : "l"(a), "l"(b));
}

// Scratch (16B-aligned)
__device__ __align__(16) float g_red[CR * NPX];        // [k][px]  k-major
__device__ __align__(16) float g_ker[4 * KKG * HW];    // [b][392][hw]

// ---------------------------------------------------------------------------
// Kernel 1: red[k][px] = sum_c x[b,c,hw] * w_reduce[k,c] + b_reduce[k]
// Block 256 thr = 8 warps; tile 64 px; warp computes 4 outs x 64 px.
// Everything staged once (x tile as px-pairs, w duplicated), 1 sync.
// ---------------------------------------------------------------------------
__global__ __launch_bounds__(256) void k_reduce(const float* __restrict__ x,
                                                const float* __restrict__ wr,
                                                const float* __restrict__ br) {
    __shared__ u64 xsd[C * 32];        // [c][p2], 32 KB
    __shared__ u64 wsd[C * 33];        // [c][o] duplicated (w,w), stride 33
    const int tid  = threadIdx.x;
    const int lane = tid & 31;
    const int warp = tid >> 5;
    const int px0  = blockIdx.x * 64;
    const int b    = px0 >> 12;
    const int hw0  = px0 & 4095;
    const float* xb = x + (size_t)b * C * HW + hw0;

#pragma unroll
    for (int l = 0; l < 16; l++) {
        int idx = tid + l * 256;               // 4096 = 128 c * 32 pairs
        int c = idx >> 5, p2 = idx & 31;
        float2 v = *(const float2*)&xb[(size_t)c * HW + 2 * p2];
        xsd[c * 32 + p2] = pack2(v.x, v.y);
    }
#pragma unroll
    for (int l = 0; l < 16; l++) {
        int idx = tid + l * 256;               // 4096 = 32 o * 128 c
        int c = idx & 127, o = idx >> 7;
        float v = wr[o * C + c];
        wsd[c * 33 + o] = pack2(v, v);
    }
    __syncthreads();

    const int wo = warp * 4;                   // warp's 4 output channels
    u64 acc[4];
#pragma unroll
    for (int j = 0; j < 4; j++) {
        float bj = br[wo + j];
        acc[j] = pack2(bj, bj);
    }

#pragma unroll 8
    for (int k = 0; k < C; k++) {
        const u64 a = xsd[k * 32 + lane];      // lane's px pair
#pragma unroll
        for (int j = 0; j < 4; j++)
            ffma2(acc[j], a, wsd[k * 33 + wo + j]);   // warp-uniform bcast
    }

#pragma unroll
    for (int j = 0; j < 4; j++) {
        float f0, f1; unpack2(acc[j], f0, f1);
        *(float2*)&g_red[(size_t)(wo + j) * NPX + px0 + 2 * lane] = make_float2(f0, f1);
    }
}

// ---------------------------------------------------------------------------
// Kernel 2: ker[b][o][hw] = sum_k red[k][px] * w_span[o][k] + b_span[o]
// R4 winning shape: 256 px x 56 outs per block (8 warps x 7 outs, 8 px/lane).
// Grid (64, 7). NO launch_bounds cap (the (256,3) cap spilled in R6).
// Staging is transpose-free now (g_red already k-major).
// ---------------------------------------------------------------------------
__global__ __launch_bounds__(256) void k_span(const float* __restrict__ wsp,
                                              const float* __restrict__ bs) {
    __shared__ float rs[CR][258];      // [k][px], EVEN pad: rows 8B-aligned
    __shared__ float ws[56 * 32];      // [o_local][k]
    const int tid  = threadIdx.x;
    const int lane = tid & 31;
    const int warp = tid >> 5;
    const int px0  = blockIdx.x * 256;
    const int o0   = blockIdx.y * 56;
    const int b    = px0 >> 12;
    const int hw0  = px0 & 4095;

    // stage red tile: straight coalesced rows (no transpose)
#pragma unroll
    for (int l = 0; l < 32; l++) {
        int idx = tid + l * 256;                  // 8192 = 32 k * 256 px
        int k = idx >> 8, px = idx & 255;
        rs[k][px] = g_red[(size_t)k * NPX + px0 + px];
    }
#pragma unroll
    for (int l = 0; l < 7; l++) {
        int idx = tid + l * 256;                  // 1792 = 56*32
        ws[idx] = wsp[o0 * 32 + idx];
    }
    __syncthreads();

    u64 acc[4][7] = {};

#pragma unroll
    for (int k = 0; k < 32; k++) {
        u64 a[4];
#pragma unroll
        for (int v = 0; v < 4; v++)
            a[v] = *(const u64*)&rs[k][2 * lane + 64 * v];
#pragma unroll
        for (int j = 0; j < 7; j++) {
            const float bv = ws[(warp * 7 + j) * 32 + k];   // uniform bcast
            const u64 b2 = pack2(bv, bv);
#pragma unroll
            for (int v = 0; v < 4; v++) ffma2(acc[v][j], a[v], b2);
        }
    }

#pragma unroll
    for (int j = 0; j < 7; j++) {
        const int o = o0 + warp * 7 + j;
        const float bias = bs[o];
        float* kp = g_ker + ((size_t)b * KKG + o) * HW + hw0;
#pragma unroll
        for (int v = 0; v < 4; v++) {
            float f0, f1; unpack2(acc[v][j], f0, f1);
            *(float2*)&kp[2 * lane + 64 * v] = make_float2(f0 + bias, f1 + bias);
        }
    }
}

// ---------------------------------------------------------------------------
// Kernel 3: involution, split-kreg variant. Block 256 (16x16), 32x16 tile.
// Taps processed in 2 halves (25 + 24) so kreg needs 50 regs, not 98.
// Per-channel f32x2 accumulators (16 u64) carried in registers across halves.
// Target ~110 regs -> 2 CTAs/SM (R4 version was 1 CTA/SM).
// ---------------------------------------------------------------------------
__global__ __launch_bounds__(256) void k_inv(const float* __restrict__ x,
                                             float* __restrict__ out) {
    __shared__ float xs[4][28][48];    // 4 channels, 28x44 patch (stride 48)
    const int tx = threadIdx.x, ty = threadIdx.y;   // (16,16)
    const int tid = ty * 16 + tx;
    const int tx0 = blockIdx.x * 32, ty0 = blockIdx.y * 16;
    const int bg = blockIdx.z;
    const int b = bg >> 3, g = bg & 7;
    const int pix = (ty0 + ty) * 64 + tx0 + 2 * tx;   // even -> 8B aligned

    const float* kb = g_ker + ((size_t)b * KKG + g * KK) * HW + pix;
    const float* xb = x + ((size_t)b * C + g * CG) * HW;
    float* ob = out + ((size_t)b * C + g * CG) * HW + pix;

    u64 accs[CG] = {};   // one f32x2 accumulator per group channel

#pragma unroll
    for (int half = 0; half < 2; half++) {
        const int t0 = half * 25;
        const int nt = half ? 24 : 25;

        u64 kreg[25];
#pragma unroll
        for (int t = 0; t < 25; t++)
            if (t < nt) kreg[t] = *(const u64*)&kb[(size_t)(t0 + t) * HW];

#pragma unroll
        for (int c0 = 0; c0 < CG; c0 += 4) {
            __syncthreads();
#pragma unroll
            for (int cc = 0; cc < 4; cc++) {
                const float* xc = xb + (size_t)(c0 + cc) * HW;
#pragma unroll
                for (int l = 0; l < 5; l++) {
                    int idx = tid + l * 256;
                    if (idx < 28 * 44) {
                        int r    = idx / 44;
                        int ccol = idx - r * 44;
                        int gy = ty0 - 6 + r;
                        int gx = tx0 - 6 + ccol;
                        float v = 0.f;
                        if (gy >= 0 && gy < 64 && gx >= 0 && gx < 64)
                            v = xc[gy * 64 + gx];
                        xs[cc][r][ccol] = v;
                    }
                }
            }
            __syncthreads();

#pragma unroll
            for (int cc = 0; cc < 4; cc++) {
                u64 a = accs[c0 + cc];
#pragma unroll
                for (int t = 0; t < 25; t++) {
                    if (t < nt) {
                        const int tt = t0 + t;
                        const int i = tt / 7, j = tt - 7 * i;
                        const u64 v = *(const u64*)&xs[cc][ty + 2 * i][2 * tx + 2 * j];
                        ffma2(a, v, kreg[t]);
                    }
                }
                accs[c0 + cc] = a;
            }
        }
    }

#pragma unroll
    for (int c = 0; c < CG; c++) {
        float f0, f1; unpack2(accs[c], f0, f1);
        *(float2*)&ob[(size_t)c * HW] = make_float2(f0, f1);
    }
}

// ---------------------------------------------------------------------------
extern "C" void kernel_launch(void* const* d_in, const int* in_sizes, int n_in,
                              void* d_out, int out_size) {
    const float* x   = (const float*)d_in[0];   // [4,128,64,64]
    const float* wr  = (const float*)d_in[1];   // [32,128]
    const float* br  = (const float*)d_in[2];   // [32]
    const float* wsp = (const float*)d_in[3];   // [392,32]
    const float* bsp = (const float*)d_in[4];   // [392]
    float* out = (float*)d_out;

    k_reduce<<<256, 256>>>(x, wr, br);
    k_span<<<dim3(64, 7), 256>>>(wsp, bsp);
    k_inv<<<dim3(2, 4, 32), dim3(16, 16)>>>(x, out);
}

// round 11
// speedup vs baseline: 1.7197x; 1.2884x over previous
#include <cuda_runtime.h>

#define HW   4096
#define C    128
#define CR   32
#define G    8
#define CG   16
#define KK   49
#define KKG  392
#define NPX  16384   // B * H * W

typedef unsigned long long u64;

// ---- packed f32x2 helpers (sm_103a) ---------------------------------------
__device__ __forceinline__ u64 pack2(float x, float y) {
    u64 r; asm("mov.b64 %0, {%1, %2};" : "=l"(r) : "f"(x), "f"(y)); return r;
}
__device__ __forceinline__ void unpack2(u64 v, float& x, float& y) {
    asm("mov.b64 {%0, %1}, %2;" : "=f"(x), "=f"(y) : "l"(v));
}
__device__ __forceinline__ void ffma2(u64& d, u64 a, u64 b) {
    asm("fma.rn.f32x2 %0, %1, %2, %0;" : "+l"(d) : "l"(a), "l"(b));
}

// Scratch (16B-aligned)
__device__ __align__(16) float g_red[CR * NPX];        // [k][px]  k-major
__device__ __align__(16) float g_ker[4 * KKG * HW];    // [b][392][hw]

// ---------------------------------------------------------------------------
// Kernel 1: red[k][px] = sum_c x[b,c,hw] * w_reduce[k,c] + b_reduce[k]
// Block 256 thr = 8 warps; tile 64 px; warp computes 4 outs x 64 px.
// (Warm-run cost is small; cold ncu time is the 8MB x DRAM fetch.)
// ---------------------------------------------------------------------------
__global__ __launch_bounds__(256) void k_reduce(const float* __restrict__ x,
                                                const float* __restrict__ wr,
                                                const float* __restrict__ br) {
    __shared__ u64 xsd[C * 32];        // [c][p2], 32 KB
    __shared__ u64 wsd[C * 33];        // [c][o] duplicated (w,w), stride 33
    const int tid  = threadIdx.x;
    const int lane = tid & 31;
    const int warp = tid >> 5;
    const int px0  = blockIdx.x * 64;
    const int b    = px0 >> 12;
    const int hw0  = px0 & 4095;
    const float* xb = x + (size_t)b * C * HW + hw0;

#pragma unroll
    for (int l = 0; l < 16; l++) {
        int idx = tid + l * 256;               // 4096 = 128 c * 32 pairs
        int c = idx >> 5, p2 = idx & 31;
        float2 v = *(const float2*)&xb[(size_t)c * HW + 2 * p2];
        xsd[c * 32 + p2] = pack2(v.x, v.y);
    }
#pragma unroll
    for (int l = 0; l < 16; l++) {
        int idx = tid + l * 256;               // 4096 = 32 o * 128 c
        int c = idx & 127, o = idx >> 7;
        float v = wr[o * C + c];
        wsd[c * 33 + o] = pack2(v, v);
    }
    __syncthreads();

    const int wo = warp * 4;                   // warp's 4 output channels
    u64 acc[4];
#pragma unroll
    for (int j = 0; j < 4; j++) {
        float bj = br[wo + j];
        acc[j] = pack2(bj, bj);
    }

#pragma unroll 8
    for (int k = 0; k < C; k++) {
        const u64 a = xsd[k * 32 + lane];      // lane's px pair
#pragma unroll
        for (int j = 0; j < 4; j++)
            ffma2(acc[j], a, wsd[k * 33 + wo + j]);   // warp-uniform bcast
    }

#pragma unroll
    for (int j = 0; j < 4; j++) {
        float f0, f1; unpack2(acc[j], f0, f1);
        *(float2*)&g_red[(size_t)(wo + j) * NPX + px0 + 2 * lane] = make_float2(f0, f1);
    }
}

// ---------------------------------------------------------------------------
// Kernel 2: ker[b][o][hw] = sum_k red[k][px] * w_span[o][k] + b_span[o]
// R4 winning shape: 256 px x 56 outs (8 warps x 7 outs, 8 px/lane), grid (64,7).
// ---------------------------------------------------------------------------
__global__ __launch_bounds__(256) void k_span(const float* __restrict__ wsp,
                                              const float* __restrict__ bs) {
    __shared__ float rs[CR][258];      // [k][px], EVEN pad: rows 8B-aligned
    __shared__ float ws[56 * 32];      // [o_local][k]
    const int tid  = threadIdx.x;
    const int lane = tid & 31;
    const int warp = tid >> 5;
    const int px0  = blockIdx.x * 256;
    const int o0   = blockIdx.y * 56;
    const int b    = px0 >> 12;
    const int hw0  = px0 & 4095;

    // stage red tile: straight coalesced rows (no transpose)
#pragma unroll
    for (int l = 0; l < 32; l++) {
        int idx = tid + l * 256;                  // 8192 = 32 k * 256 px
        int k = idx >> 8, px = idx & 255;
        rs[k][px] = g_red[(size_t)k * NPX + px0 + px];
    }
#pragma unroll
    for (int l = 0; l < 7; l++) {
        int idx = tid + l * 256;                  // 1792 = 56*32
        ws[idx] = wsp[o0 * 32 + idx];
    }
    __syncthreads();

    u64 acc[4][7] = {};

#pragma unroll
    for (int k = 0; k < 32; k++) {
        u64 a[4];
#pragma unroll
        for (int v = 0; v < 4; v++)
            a[v] = *(const u64*)&rs[k][2 * lane + 64 * v];
#pragma unroll
        for (int j = 0; j < 7; j++) {
            const float bv = ws[(warp * 7 + j) * 32 + k];   // uniform bcast
            const u64 b2 = pack2(bv, bv);
#pragma unroll
            for (int v = 0; v < 4; v++) ffma2(acc[v][j], a[v], b2);
        }
    }

#pragma unroll
    for (int j = 0; j < 7; j++) {
        const int o = o0 + warp * 7 + j;
        const float bias = bs[o];
        float* kp = g_ker + ((size_t)b * KKG + o) * HW + hw0;
#pragma unroll
        for (int v = 0; v < 4; v++) {
            float f0, f1; unpack2(acc[v][j], f0, f1);
            *(float2*)&kp[2 * lane + 64 * v] = make_float2(f0 + bias, f1 + bias);
        }
    }
}

// ---------------------------------------------------------------------------
// Kernel 3: involution (R4 structure + dual accumulators + ping-pong staging).
// Block 256 (16x16), 32x16 px tile, one (b,g) per z-block. Thread owns 2 px.
// kreg[49] f32x2 in registers, reused across 16 channels (R4-proven).
// NEW: taps split across 2 accumulators (breaks 49-long FFMA2 dep chain);
//      channels staged 2-per-buffer ping-pong with prefetch-to-regs so LDG
//      latency of round r+1 hides behind compute of round r (1 sync/round).
// ---------------------------------------------------------------------------
__global__ __launch_bounds__(256) void k_inv(const float* __restrict__ x,
                                             float* __restrict__ out) {
    __shared__ float xs[2][2][28][48];   // [buf][ch][row][col], 21.5 KB
    const int tx = threadIdx.x, ty = threadIdx.y;   // (16,16)
    const int tid = ty * 16 + tx;
    const int tx0 = blockIdx.x * 32, ty0 = blockIdx.y * 16;
    const int bg = blockIdx.z;
    const int b = bg >> 3, g = bg & 7;
    const int pix = (ty0 + ty) * 64 + tx0 + 2 * tx;   // even -> 8B aligned

    // 49 per-pixel kernel pairs -> registers (coalesced LDG.64)
    const float* kb = g_ker + ((size_t)b * KKG + g * KK) * HW + pix;
    u64 kreg[49];
#pragma unroll
    for (int kk = 0; kk < 49; kk++) kreg[kk] = *(const u64*)&kb[(size_t)kk * HW];

    const float* xb = x + ((size_t)b * C + g * CG) * HW;
    float* ob = out + ((size_t)b * C + g * CG) * HW + pix;

    // staging geometry: 28 rows x 44 cols = 1232 elems, 5 iters of 256 thr
    const int sr = (tid + 0 * 256) / 44;   // recomputed per l below

    // ---- prime buffer 0 with channels 0,1 ----
#pragma unroll
    for (int cc = 0; cc < 2; cc++) {
        const float* xc = xb + (size_t)cc * HW;
#pragma unroll
        for (int l = 0; l < 5; l++) {
            int idx = tid + l * 256;
            if (idx < 28 * 44) {
                int r    = idx / 44;
                int ccol = idx - r * 44;
                int gy = ty0 - 6 + r;
                int gx = tx0 - 6 + ccol;
                float v = 0.f;
                if (gy >= 0 && gy < 64 && gx >= 0 && gx < 64)
                    v = xc[gy * 64 + gx];
                xs[0][cc][r][ccol] = v;
            }
        }
    }
    __syncthreads();

    for (int rnd = 0; rnd < 8; rnd++) {
        const int cur = rnd & 1;
        const int c0  = rnd * 2;

        // prefetch next round's 2 channels into registers (LDG in flight
        // while we compute below)
        float pf[10];
        if (rnd < 7) {
#pragma unroll
            for (int cc = 0; cc < 2; cc++) {
                const float* xc = xb + (size_t)(c0 + 2 + cc) * HW;
#pragma unroll
                for (int l = 0; l < 5; l++) {
                    int idx = tid + l * 256;
                    float v = 0.f;
                    if (idx < 28 * 44) {
                        int r    = idx / 44;
                        int ccol = idx - r * 44;
                        int gy = ty0 - 6 + r;
                        int gx = tx0 - 6 + ccol;
                        if (gy >= 0 && gy < 64 && gx >= 0 && gx < 64)
                            v = xc[gy * 64 + gx];
                    }
                    pf[cc * 5 + l] = v;
                }
            }
        }

        // compute the 2 current channels; taps split over 2 accumulators
#pragma unroll
        for (int cc = 0; cc < 2; cc++) {
            u64 a0 = 0, a1 = 0;
#pragma unroll
            for (int i = 0; i < 7; i++)
#pragma unroll
                for (int j = 0; j < 7; j++) {
                    const int t = i * 7 + j;
                    const u64 v = *(const u64*)&xs[cur][cc][ty + 2 * i][2 * tx + 2 * j];
                    if (t & 1) ffma2(a1, v, kreg[t]);
                    else       ffma2(a0, v, kreg[t]);
                }
            float e0, e1, o0, o1;
            unpack2(a0, e0, e1); unpack2(a1, o0, o1);
            *(float2*)&ob[(size_t)(c0 + cc) * HW] = make_float2(e0 + o0, e1 + o1);
        }

        // commit prefetched data into the other buffer
        if (rnd < 7) {
#pragma unroll
            for (int cc = 0; cc < 2; cc++)
#pragma unroll
                for (int l = 0; l < 5; l++) {
                    int idx = tid + l * 256;
                    if (idx < 28 * 44) {
                        int r    = idx / 44;
                        int ccol = idx - r * 44;
                        xs[1 - cur][cc][r][ccol] = pf[cc * 5 + l];
                    }
                }
            __syncthreads();
        }
    }
    (void)sr;
}

// ---------------------------------------------------------------------------
extern "C" void kernel_launch(void* const* d_in, const int* in_sizes, int n_in,
                              void* d_out, int out_size) {
    const float* x   = (const float*)d_in[0];   // [4,128,64,64]
    const float* wr  = (const float*)d_in[1];   // [32,128]
    const float* br  = (const float*)d_in[2];   // [32]
    const float* wsp = (const float*)d_in[3];   // [392,32]
    const float* bsp = (const float*)d_in[4];   // [392]
    float* out = (float*)d_out;

    k_reduce<<<256, 256>>>(x, wr, br);
    k_span<<<dim3(64, 7), 256>>>(wsp, bsp);
    k_inv<<<dim3(2, 4, 32), dim3(16, 16)>>>(x, out);
}